// round 1
// baseline (speedup 1.0000x reference)
#include <cuda_runtime.h>
#include <cstdint>

// Problem constants
#define NN 128      // frames
#define PP 256      // points
#define DD 128      // input dim
#define HEADS 16
#define HD 16
#define ODIM 256    // HD*HEADS
#define HIDDEN 2048
#define ROWS (NN*PP)   // 32768

// Scratch (device globals; no cudaMalloc allowed)
__device__ float g_y1[(size_t)ROWS * 768];   // qkv1: [r][q*256 + a*16+b], r=i*256+j
__device__ float g_t [(size_t)ROWS * 256];   // t:    [r][h*16+m]
__device__ float g_y2[(size_t)ROWS * 768];   // qkv2: [r][q*256 + g*16+n]
__device__ float g_pa[(size_t)ROWS * 256];   // pa:   [r][a*16+b]
__device__ float g_h [(size_t)ROWS * 2048];  // fc1 out

// ---------------------------------------------------------------------------
// Generic tiled SGEMM: C[M,N] = A[M,K] @ B[K,N] (+bias), all row-major.
// BM=BN=128, BK=16, 256 threads, 8x8 per thread. Dims must divide tiles
// (they do for every call here).
// ---------------------------------------------------------------------------
__global__ __launch_bounds__(256) void sgemm128(
    const float* __restrict__ A, const float* __restrict__ B,
    float* __restrict__ C, const float* __restrict__ bias,
    int M, int N, int K, int lda, int ldb, int ldc)
{
    __shared__ float As[16][132];   // [k][m], padded
    __shared__ float Bs[16][128];   // [k][n]

    const int tid = threadIdx.x;
    const int tx = tid & 15;        // 0..15 -> 8 cols each
    const int ty = tid >> 4;        // 0..15 -> 8 rows each
    const int bm = blockIdx.y * 128;
    const int bn = blockIdx.x * 128;

    float acc[8][8];
    #pragma unroll
    for (int i = 0; i < 8; i++)
        #pragma unroll
        for (int j = 0; j < 8; j++) acc[i][j] = 0.f;

    for (int k0 = 0; k0 < K; k0 += 16) {
        // A tile: 128 rows x 16 cols = 512 float4
        #pragma unroll
        for (int l = 0; l < 2; l++) {
            int idx = tid + l * 256;
            int r   = idx >> 2;
            int c4  = (idx & 3) * 4;
            float4 a4 = *(const float4*)(A + (size_t)(bm + r) * lda + k0 + c4);
            As[c4 + 0][r] = a4.x;
            As[c4 + 1][r] = a4.y;
            As[c4 + 2][r] = a4.z;
            As[c4 + 3][r] = a4.w;
        }
        // B tile: 16 rows x 128 cols = 512 float4
        #pragma unroll
        for (int l = 0; l < 2; l++) {
            int idx = tid + l * 256;
            int r   = idx >> 5;
            int c4  = (idx & 31) * 4;
            *(float4*)(&Bs[r][c4]) =
                *(const float4*)(B + (size_t)(k0 + r) * ldb + bn + c4);
        }
        __syncthreads();

        #pragma unroll
        for (int kk = 0; kk < 16; kk++) {
            float ra[8], rb[8];
            *(float4*)(ra)     = *(const float4*)(&As[kk][ty * 8]);
            *(float4*)(ra + 4) = *(const float4*)(&As[kk][ty * 8 + 4]);
            *(float4*)(rb)     = *(const float4*)(&Bs[kk][tx * 8]);
            *(float4*)(rb + 4) = *(const float4*)(&Bs[kk][tx * 8 + 4]);
            #pragma unroll
            for (int i = 0; i < 8; i++)
                #pragma unroll
                for (int j = 0; j < 8; j++)
                    acc[i][j] += ra[i] * rb[j];
        }
        __syncthreads();
    }

    float bv[8];
    if (bias) {
        *(float4*)(bv)     = *(const float4*)(bias + bn + tx * 8);
        *(float4*)(bv + 4) = *(const float4*)(bias + bn + tx * 8 + 4);
    } else {
        #pragma unroll
        for (int j = 0; j < 8; j++) bv[j] = 0.f;
    }

    #pragma unroll
    for (int i = 0; i < 8; i++) {
        float* cp = C + (size_t)(bm + ty * 8 + i) * ldc + bn + tx * 8;
        float4 o0, o1;
        o0.x = acc[i][0] + bv[0]; o0.y = acc[i][1] + bv[1];
        o0.z = acc[i][2] + bv[2]; o0.w = acc[i][3] + bv[3];
        o1.x = acc[i][4] + bv[4]; o1.y = acc[i][5] + bv[5];
        o1.z = acc[i][6] + bv[6]; o1.w = acc[i][7] + bv[7];
        *(float4*)(cp)     = o0;
        *(float4*)(cp + 4) = o1;
    }
}

// ---------------------------------------------------------------------------
// Temporal attention. Block = (j, a); 128 threads, thread = frame i.
//   s(i,I) = sum_b q[a,b,i,j] * k[a,b,I,j]; softmax over I;
//   t[a,b,i,j] = sum_I p(i,I) * v[a,b,I,j]
// y1 layout: [r=(I*256+j)][q*256 + a*16 + b]
// t  layout: [r=(i*256+j)][a*16 + b]
// ---------------------------------------------------------------------------
__global__ __launch_bounds__(128) void temporal_attn(
    const float* __restrict__ y1, float* __restrict__ t_out)
{
    const int j = blockIdx.x;
    const int a = blockIdx.y;
    const int i = threadIdx.x;   // frame index (also loader index I=i)

    __shared__ float ks[16][128];
    __shared__ float vs[16][128];

    const float* base = y1 + ((size_t)i * 256 + j) * 768 + a * 16;
    float qr[16];
    #pragma unroll
    for (int c = 0; c < 4; c++) {
        float4 q4 = *(const float4*)(base + c * 4);
        qr[c * 4 + 0] = q4.x; qr[c * 4 + 1] = q4.y;
        qr[c * 4 + 2] = q4.z; qr[c * 4 + 3] = q4.w;
        float4 k4 = *(const float4*)(base + 256 + c * 4);
        ks[c * 4 + 0][i] = k4.x; ks[c * 4 + 1][i] = k4.y;
        ks[c * 4 + 2][i] = k4.z; ks[c * 4 + 3][i] = k4.w;
        float4 v4 = *(const float4*)(base + 512 + c * 4);
        vs[c * 4 + 0][i] = v4.x; vs[c * 4 + 1][i] = v4.y;
        vs[c * 4 + 2][i] = v4.z; vs[c * 4 + 3][i] = v4.w;
    }
    __syncthreads();

    float m = -1e30f, l = 0.f;
    float o[16];
    #pragma unroll
    for (int b = 0; b < 16; b++) o[b] = 0.f;

    for (int I = 0; I < 128; I++) {
        float s = 0.f;
        #pragma unroll
        for (int b = 0; b < 16; b++) s += qr[b] * ks[b][I];
        float mn = fmaxf(m, s);
        float sc = __expf(m - mn);
        float e  = __expf(s - mn);
        l = l * sc + e;
        #pragma unroll
        for (int b = 0; b < 16; b++) o[b] = o[b] * sc + e * vs[b][I];
        m = mn;
    }
    float inv = 1.f / l;
    float* op = t_out + ((size_t)i * 256 + j) * 256 + a * 16;
    #pragma unroll
    for (int c = 0; c < 4; c++) {
        float4 w;
        w.x = o[c * 4 + 0] * inv; w.y = o[c * 4 + 1] * inv;
        w.z = o[c * 4 + 2] * inv; w.w = o[c * 4 + 3] * inv;
        *(float4*)(op + c * 4) = w;
    }
}

// ---------------------------------------------------------------------------
// Point attention. Block = (i, a); 256 threads, thread = point j.
//   s(j,J) = sum_b q2[a,b,i,j] * k2[a,b,i,J]; softmax over J;
//   pa[i,j,a,b] = sum_J p(j,J) * v2[a,b,i,J]
// y2 layout: [r=(i*256+J)][q*256 + a*16 + b]
// pa layout: [r=(i*256+j)][a*16 + b]
// ---------------------------------------------------------------------------
__global__ __launch_bounds__(256) void point_attn(
    const float* __restrict__ y2, float* __restrict__ pa_out)
{
    const int i = blockIdx.x;
    const int a = blockIdx.y;
    const int j = threadIdx.x;   // point index (also loader index J=j)

    __shared__ float ks[16][256];
    __shared__ float vs[16][256];

    const float* base = y2 + ((size_t)i * 256 + j) * 768 + a * 16;
    float qr[16];
    #pragma unroll
    for (int c = 0; c < 4; c++) {
        float4 q4 = *(const float4*)(base + c * 4);
        qr[c * 4 + 0] = q4.x; qr[c * 4 + 1] = q4.y;
        qr[c * 4 + 2] = q4.z; qr[c * 4 + 3] = q4.w;
        float4 k4 = *(const float4*)(base + 256 + c * 4);
        ks[c * 4 + 0][j] = k4.x; ks[c * 4 + 1][j] = k4.y;
        ks[c * 4 + 2][j] = k4.z; ks[c * 4 + 3][j] = k4.w;
        float4 v4 = *(const float4*)(base + 512 + c * 4);
        vs[c * 4 + 0][j] = v4.x; vs[c * 4 + 1][j] = v4.y;
        vs[c * 4 + 2][j] = v4.z; vs[c * 4 + 3][j] = v4.w;
    }
    __syncthreads();

    float m = -1e30f, l = 0.f;
    float o[16];
    #pragma unroll
    for (int b = 0; b < 16; b++) o[b] = 0.f;

    for (int J = 0; J < 256; J++) {
        float s = 0.f;
        #pragma unroll
        for (int b = 0; b < 16; b++) s += qr[b] * ks[b][J];
        float mn = fmaxf(m, s);
        float sc = __expf(m - mn);
        float e  = __expf(s - mn);
        l = l * sc + e;
        #pragma unroll
        for (int b = 0; b < 16; b++) o[b] = o[b] * sc + e * vs[b][J];
        m = mn;
    }
    float inv = 1.f / l;
    float* op = pa_out + ((size_t)i * 256 + j) * 256 + a * 16;
    #pragma unroll
    for (int c = 0; c < 4; c++) {
        float4 w;
        w.x = o[c * 4 + 0] * inv; w.y = o[c * 4 + 1] * inv;
        w.z = o[c * 4 + 2] * inv; w.w = o[c * 4 + 3] * inv;
        *(float4*)(op + c * 4) = w;
    }
}

// ---------------------------------------------------------------------------

extern "C" void kernel_launch(void* const* d_in, const int* in_sizes, int n_in,
                              void* d_out, int out_size)
{
    const float* x     = (const float*)d_in[0];  // (128,256,128)
    const float* W1    = (const float*)d_in[1];  // (3,128,16,16)
    const float* W2    = (const float*)d_in[2];  // (3,16,16,16,16)
    const float* fc1_w = (const float*)d_in[3];  // (256,2048)
    const float* fc1_b = (const float*)d_in[4];  // (2048,)
    const float* fc2_w = (const float*)d_in[5];  // (2048,256)
    const float* fc2_b = (const float*)d_in[6];  // (256,)
    float* out = (float*)d_out;                  // (128,256,256)

    float *y1, *t, *y2, *pa, *h;
    cudaGetSymbolAddress((void**)&y1, g_y1);
    cudaGetSymbolAddress((void**)&t,  g_t);
    cudaGetSymbolAddress((void**)&y2, g_y2);
    cudaGetSymbolAddress((void**)&pa, g_pa);
    cudaGetSymbolAddress((void**)&h,  g_h);

    // 1) QKV1: 3 x (32768x128)@(128x256) -> y1 columns [q*256, q*256+256)
    for (int q = 0; q < 3; q++) {
        sgemm128<<<dim3(256 / 128, ROWS / 128), 256>>>(
            x, W1 + (size_t)q * DD * 256, y1 + q * 256, nullptr,
            ROWS, 256, DD, DD, 256, 768);
    }

    // 2) Temporal attention: 4096 blocks (j, a)
    temporal_attn<<<dim3(PP, HD), 128>>>(y1, t);

    // 3) QKV2: 3 x (32768x256)@(256x256) -> y2 columns
    for (int q = 0; q < 3; q++) {
        sgemm128<<<dim3(256 / 128, ROWS / 128), 256>>>(
            t, W2 + (size_t)q * 256 * 256, y2 + q * 256, nullptr,
            ROWS, 256, 256, 256, 256, 768);
    }

    // 4) Point attention: 2048 blocks (i, a)
    point_attn<<<dim3(NN, HD), 256>>>(y2, pa);

    // 5) FC1: (32768x256)@(256x2048) + b
    sgemm128<<<dim3(HIDDEN / 128, ROWS / 128), 256>>>(
        pa, fc1_w, h, fc1_b, ROWS, HIDDEN, 256, 256, HIDDEN, HIDDEN);

    // 6) FC2: (32768x2048)@(2048x256) + b -> output
    sgemm128<<<dim3(256 / 128, ROWS / 128), 256>>>(
        h, fc2_w, out, fc2_b, ROWS, 256, HIDDEN, HIDDEN, 256, 256);
}